// round 5
// baseline (speedup 1.0000x reference)
#include <cuda_runtime.h>
#include <cuda_bf16.h>
#include <math.h>

// ForwardBackwardImputer: out[b,t,:] = x[b, idx_fwd[b,t], :]
// mask[t] = all(|x[b,t,d]| <= 1e-6); idx_fwd = inclusive cummax(mask ? 0 : t).
// (Backward-fill branch of the reference is provably identical to x_fwd.)
//
// Two kernels:
//   A: flattened, load-balanced mask + copy-through of valid rows (bulk traffic)
//   B: per-batch-row scan + gather fill of the ~10% missing rows

#define L_SEQ 2048
#define D_FEAT 128
#define ROW_F4 (D_FEAT / 4)   // 32 float4 per timestep row
#define ATOL_F 1e-6f

#define A_THREADS 256
#define A_WARPS   8
#define A_GRID    1184        // 148 SMs * 8; ~1.6 waves at 5 CTAs/SM -> balanced

#define B_THREADS 512
#define B_WARPS   16

// Max problem we support: 1024 batch rows of 2048 steps (2 MB).
__device__ unsigned char g_mask[1024 * L_SEQ];

// ---------------- Kernel A: mask + streaming copy-through ------------------
__global__ __launch_bounds__(A_THREADS)
void mask_copy_kernel(const float4* __restrict__ x, float4* __restrict__ out,
                      int ngroups) {   // ngroups = (B*L)/4
    const int lane = threadIdx.x & 31;
    const int wid  = threadIdx.x >> 5;
    const unsigned FULL = 0xffffffffu;
    const int totalW = gridDim.x * A_WARPS;

    for (int g = blockIdx.x * A_WARPS + wid; g < ngroups; g += totalW) {
        const int r0 = g << 2;  // flattened (b*L + t) row base
        float4 v0 = x[(r0 + 0) * ROW_F4 + lane];
        float4 v1 = x[(r0 + 1) * ROW_F4 + lane];
        float4 v2 = x[(r0 + 2) * ROW_F4 + lane];
        float4 v3 = x[(r0 + 3) * ROW_F4 + lane];

        bool z0 = (fabsf(v0.x) <= ATOL_F) & (fabsf(v0.y) <= ATOL_F) &
                  (fabsf(v0.z) <= ATOL_F) & (fabsf(v0.w) <= ATOL_F);
        bool z1 = (fabsf(v1.x) <= ATOL_F) & (fabsf(v1.y) <= ATOL_F) &
                  (fabsf(v1.z) <= ATOL_F) & (fabsf(v1.w) <= ATOL_F);
        bool z2 = (fabsf(v2.x) <= ATOL_F) & (fabsf(v2.y) <= ATOL_F) &
                  (fabsf(v2.z) <= ATOL_F) & (fabsf(v2.w) <= ATOL_F);
        bool z3 = (fabsf(v3.x) <= ATOL_F) & (fabsf(v3.y) <= ATOL_F) &
                  (fabsf(v3.z) <= ATOL_F) & (fabsf(v3.w) <= ATOL_F);

        unsigned m0 = __all_sync(FULL, z0);
        unsigned m1 = __all_sync(FULL, z1);
        unsigned m2 = __all_sync(FULL, z2);
        unsigned m3 = __all_sync(FULL, z3);

        // Valid rows: write straight through (streaming; never re-read).
        if (!m0) __stcs(&out[(r0 + 0) * ROW_F4 + lane], v0);
        if (!m1) __stcs(&out[(r0 + 1) * ROW_F4 + lane], v1);
        if (!m2) __stcs(&out[(r0 + 2) * ROW_F4 + lane], v2);
        if (!m3) __stcs(&out[(r0 + 3) * ROW_F4 + lane], v3);

        if (lane == 0) {
            uchar4 mm = make_uchar4((unsigned char)m0, (unsigned char)m1,
                                    (unsigned char)m2, (unsigned char)m3);
            *reinterpret_cast<uchar4*>(&g_mask[r0]) = mm;
        }
    }
}

// ---------------- Kernel B: per-row scan + gather fill ---------------------
__global__ __launch_bounds__(B_THREADS, 2)
void fill_kernel(const float* __restrict__ x, float* __restrict__ out) {
    const int b = blockIdx.x;
    const float4* __restrict__ xb =
        reinterpret_cast<const float4*>(x + (size_t)b * L_SEQ * D_FEAT);
    float4* __restrict__ ob =
        reinterpret_cast<float4*>(out + (size_t)b * L_SEQ * D_FEAT);

    __shared__ unsigned char s_mask[L_SEQ];
    __shared__ short s_idx[L_SEQ];
    __shared__ int s_wtot[B_WARPS];

    const int tid  = threadIdx.x;
    const int lane = tid & 31;
    const int wid  = tid >> 5;
    const unsigned FULL = 0xffffffffu;

    // Load mask row (2 KB) coalesced.
    const uchar4* gm = reinterpret_cast<const uchar4*>(&g_mask[b * L_SEQ]);
    reinterpret_cast<uchar4*>(s_mask)[tid] = gm[tid];
    __syncthreads();

    // Block-wide inclusive max-scan of (mask ? 0 : t), 4 steps per thread.
    const int t0 = tid << 2;
    int vloc[4];
    int run = 0;
    #pragma unroll
    for (int i = 0; i < 4; i++) {
        int t = t0 + i;
        int v = s_mask[t] ? 0 : t;
        if (v > run) run = v;
        vloc[i] = run;
    }

    int incl = run;
    #pragma unroll
    for (int o = 1; o < 32; o <<= 1) {
        int n = __shfl_up_sync(FULL, incl, o);
        if (lane >= o && n > incl) incl = n;
    }
    if (lane == 31) s_wtot[wid] = incl;
    int pre = __shfl_up_sync(FULL, incl, 1);
    int texcl = (lane == 0) ? 0 : pre;
    __syncthreads();

    if (tid == 0) {
        int r = 0;
        #pragma unroll
        for (int w = 0; w < B_WARPS; w++) {
            int tmp = s_wtot[w];
            s_wtot[w] = r;
            if (tmp > r) r = tmp;
        }
    }
    __syncthreads();

    int base = s_wtot[wid];
    if (texcl > base) base = texcl;
    #pragma unroll
    for (int i = 0; i < 4; i++) {
        int v = vloc[i] > base ? vloc[i] : base;
        s_idx[t0 + i] = (short)v;
    }
    __syncthreads();

    // Gather-fill missing rows only (~10%).
    for (int tt = wid << 2; tt < L_SEQ; tt += (B_WARPS << 2)) {
        uchar4 mm = *reinterpret_cast<const uchar4*>(&s_mask[tt]);
        if (mm.x) __stcs(&ob[(tt + 0) * ROW_F4 + lane],
                         xb[(int)s_idx[tt + 0] * ROW_F4 + lane]);
        if (mm.y) __stcs(&ob[(tt + 1) * ROW_F4 + lane],
                         xb[(int)s_idx[tt + 1] * ROW_F4 + lane]);
        if (mm.z) __stcs(&ob[(tt + 2) * ROW_F4 + lane],
                         xb[(int)s_idx[tt + 2] * ROW_F4 + lane]);
        if (mm.w) __stcs(&ob[(tt + 3) * ROW_F4 + lane],
                         xb[(int)s_idx[tt + 3] * ROW_F4 + lane]);
    }
}

extern "C" void kernel_launch(void* const* d_in, const int* in_sizes, int n_in,
                              void* d_out, int out_size) {
    const float* x = (const float*)d_in[0];
    float* out = (float*)d_out;
    const int B = in_sizes[0] / (L_SEQ * D_FEAT);
    const int ngroups = (B * L_SEQ) >> 2;

    mask_copy_kernel<<<A_GRID, A_THREADS>>>(
        reinterpret_cast<const float4*>(x),
        reinterpret_cast<float4*>(out), ngroups);
    fill_kernel<<<B, B_THREADS>>>(x, out);
}